// round 7
// baseline (speedup 1.0000x reference)
#include <cuda_runtime.h>
#include <cstdint>
#include <cstddef>

// Fused LSTM: T=512, B=64, I=512, H=512, fp32.
// Kernel 1: transpose x -> xT[t][i][b]
// Kernel 2: persistent fused kernel, 128 blocks x 256 threads.
//   warps 0-3: h-GEMM (recurrent, flag-gated)   warps 4-7: x-GEMM (independent)

#define TT   512
#define BB   64
#define HH   512

typedef unsigned long long ull;

__device__ float    g_xT[(size_t)TT * HH * BB];      // 64 MB, [t][i][b]
__device__ float    g_hbuf[2][HH * BB];              // [k][b], double buffered
__device__ unsigned g_flags[128];                    // monotonic per-block step flags

// ---------------- helpers ----------------
__device__ __forceinline__ ull fma2(ull a, ull b, ull c) {
    ull d;
    asm("fma.rn.f32x2 %0, %1, %2, %3;" : "=l"(d) : "l"(a), "l"(b), "l"(c));
    return d;
}
__device__ __forceinline__ float2 unpack2(ull v) {
    float2 r;
    asm("mov.b64 {%0, %1}, %2;" : "=f"(r.x), "=f"(r.y) : "l"(v));
    return r;
}
__device__ __forceinline__ unsigned ld_acq(const unsigned* p) {
    unsigned v;
    asm volatile("ld.global.acquire.gpu.u32 %0, [%1];" : "=r"(v) : "l"(p));
    return v;
}
__device__ __forceinline__ void st_rel(unsigned* p, unsigned v) {
    asm volatile("st.global.release.gpu.u32 [%0], %1;" :: "l"(p), "r"(v));
}
__device__ __forceinline__ void barx(int id) {  // named barrier, 128 threads
    asm volatile("bar.sync %0, 128;" :: "r"(id) : "memory");
}
__device__ __forceinline__ float sigm(float x) {
    return 1.0f / (1.0f + __expf(-x));
}

// ---------------- Kernel 1: x transpose to [t][i][b] ----------------
__global__ void __launch_bounds__(256) xT_kernel(const float* __restrict__ x)
{
    __shared__ float ts[64][65];
    const int t  = blockIdx.y;
    const int i0 = blockIdx.x * 64;
    const int tid = threadIdx.x;
#pragma unroll
    for (int p = 0; p < 16; ++p) {
        int lin = p * 256 + tid;
        int b = lin >> 6, i = lin & 63;
        ts[i][b] = x[((size_t)t * BB + b) * HH + i0 + i];
    }
    __syncthreads();
#pragma unroll
    for (int p = 0; p < 16; ++p) {
        int lin = p * 256 + tid;
        int i = lin >> 6, b = lin & 63;
        g_xT[((size_t)t * HH + i0 + i) * BB + b] = ts[i][b];
    }
}

// ---------------- Kernel 2: fused persistent LSTM ----------------
// SMEM float offsets:
//   Wd     [512][16] float2 (w,w)   : 0      .. 16383
//   Xd     [512][16] float2         : 16384  .. 32767
//   hs     [128][64]                : 32768  .. 40959
//   xs     [128][64]                : 40960  .. 49151
//   gate_h [16][64]                 : 49152  .. 50175
//   gate_x [16][64]                 : 50176  .. 51199
//   hout   [4][64]                  : 51200  .. 51455
//   bias   [16]                     : 51456  .. 51471
#define SM_TOTAL_FLOATS 51472

__global__ void __launch_bounds__(256, 1) lstm_fused_kernel(
    const float* __restrict__ Wih,   // [4H][I]
    const float* __restrict__ Whh,   // [4H][H]
    const float* __restrict__ bih,
    const float* __restrict__ bhh,
    float* __restrict__ out)         // [T][B][H]
{
    extern __shared__ float sm[];
    float* Wd     = sm;
    float* Xd     = sm + 16384;
    float* hs     = sm + 32768;
    float* xs     = sm + 40960;
    float* gate_h = sm + 49152;
    float* gate_x = sm + 50176;
    float* hout   = sm + 51200;
    float* bias_s = sm + 51456;

    const int tid  = threadIdx.x;
    const int bid  = blockIdx.x;
    const int j0   = bid * 4;
    const int grp  = tid >> 7;        // 0 = h-group, 1 = x-group
    const int gtid = tid & 127;
    const int wg   = gtid >> 5;       // 0..3 within group
    const int lane = gtid & 31;

    // compute-tile mapping: warp covers 8 row-pairs x 32 batches
    const int r0 = (wg & 1) * 8 + ((lane >> 3) << 1);        // 0,2,..,14
    const int b4 = (wg >> 1) * 32 + ((lane & 7) << 2);       // 0,4,..,60

    // ---- init: load W slices duplicated (w,w), bias ----
    {
        int r = gtid >> 3, seg = gtid & 7;  // r 0..15, seg 0..7 (k-chunk of 64)
        int grow = (r >> 2) * HH + j0 + (r & 3);
        const float* src = (grp == 0 ? Whh : Wih) + (size_t)grow * HH + seg * 64;
        float2* dst = (float2*)(grp == 0 ? Wd : Xd);
#pragma unroll
        for (int q = 0; q < 64; q += 4) {
            float4 v = *(const float4*)(src + q);
            int k = seg * 64 + q;
            dst[(k + 0) * 16 + r] = make_float2(v.x, v.x);
            dst[(k + 1) * 16 + r] = make_float2(v.y, v.y);
            dst[(k + 2) * 16 + r] = make_float2(v.z, v.z);
            dst[(k + 3) * 16 + r] = make_float2(v.w, v.w);
        }
    }
    if (tid < 16) {
        int grow = (tid >> 2) * HH + j0 + (tid & 3);
        bias_s[tid] = bih[grow] + bhh[grow];
    }

    __shared__ unsigned s_base;
    if (tid == 0) s_base = ld_acq(&g_flags[bid]);
    __syncthreads();
    const unsigned base = s_base;

    // epilogue mapping + register cell state
    const int jj = (tid >> 6) & 3;
    const int be = tid & 63;
    float c_reg = 0.0f;

    for (int t = 0; t < TT; ++t) {
        ull a0 = 0, a1 = 0, a2 = 0, a3 = 0;

        if (grp == 0) {
            // ---------------- h-GEMM group ----------------
            if (t > 0) {
                if (wg == 0) {   // warp 0 polls all 128 flags
                    unsigned tgt = base + (unsigned)t;
                    for (;;) {
                        unsigned v0 = ld_acq(&g_flags[lane]);
                        unsigned v1 = ld_acq(&g_flags[lane + 32]);
                        unsigned v2 = ld_acq(&g_flags[lane + 64]);
                        unsigned v3 = ld_acq(&g_flags[lane + 96]);
                        bool ok = ((int)(v0 - tgt) >= 0) & ((int)(v1 - tgt) >= 0) &
                                  ((int)(v2 - tgt) >= 0) & ((int)(v3 - tgt) >= 0);
                        if (__all_sync(0xffffffffu, ok)) break;
                        __nanosleep(32);
                    }
                }
                barx(1);

                const float4* hsrc = (const float4*)(g_hbuf[(t + 1) & 1]);
                float4 pre[16];
#pragma unroll
                for (int i = 0; i < 16; ++i)
                    pre[i] = __ldcg(hsrc + gtid + i * 128);

                for (int kt = 0; kt < 4; ++kt) {
#pragma unroll
                    for (int i = 0; i < 16; ++i)
                        ((float4*)hs)[gtid + i * 128] = pre[i];
                    barx(1);
                    if (kt < 3) {
#pragma unroll
                        for (int i = 0; i < 16; ++i)
                            pre[i] = __ldcg(hsrc + (kt + 1) * 2048 + gtid + i * 128);
                    }
#pragma unroll 8
                    for (int k = 0; k < 128; ++k) {
                        ulonglong2 wp = *(const ulonglong2*)&Wd[((kt * 128 + k) * 16 + r0) * 2];
                        ulonglong2 hp = *(const ulonglong2*)&hs[k * 64 + b4];
                        a0 = fma2(hp.x, wp.x, a0);
                        a1 = fma2(hp.y, wp.x, a1);
                        a2 = fma2(hp.x, wp.y, a2);
                        a3 = fma2(hp.y, wp.y, a3);
                    }
                    barx(1);
                }
            }
            // scatter partials
            float2 v;
            v = unpack2(a0); gate_h[r0 * 64 + b4 + 0] = v.x; gate_h[r0 * 64 + b4 + 1] = v.y;
            v = unpack2(a1); gate_h[r0 * 64 + b4 + 2] = v.x; gate_h[r0 * 64 + b4 + 3] = v.y;
            v = unpack2(a2); gate_h[(r0 + 1) * 64 + b4 + 0] = v.x; gate_h[(r0 + 1) * 64 + b4 + 1] = v.y;
            v = unpack2(a3); gate_h[(r0 + 1) * 64 + b4 + 2] = v.x; gate_h[(r0 + 1) * 64 + b4 + 3] = v.y;
        } else {
            // ---------------- x-GEMM group ----------------
            const float4* xsrc = (const float4*)(g_xT + (size_t)t * (HH * BB));
            float4 pre[16];
#pragma unroll
            for (int i = 0; i < 16; ++i)
                pre[i] = __ldcs(xsrc + gtid + i * 128);

            for (int kt = 0; kt < 4; ++kt) {
#pragma unroll
                for (int i = 0; i < 16; ++i)
                    ((float4*)xs)[gtid + i * 128] = pre[i];
                barx(2);
                if (kt < 3) {
#pragma unroll
                    for (int i = 0; i < 16; ++i)
                        pre[i] = __ldcs(xsrc + (kt + 1) * 2048 + gtid + i * 128);
                }
#pragma unroll 8
                for (int k = 0; k < 128; ++k) {
                    ulonglong2 wp = *(const ulonglong2*)&Xd[((kt * 128 + k) * 16 + r0) * 2];
                    ulonglong2 hp = *(const ulonglong2*)&xs[k * 64 + b4];
                    a0 = fma2(hp.x, wp.x, a0);
                    a1 = fma2(hp.y, wp.x, a1);
                    a2 = fma2(hp.x, wp.y, a2);
                    a3 = fma2(hp.y, wp.y, a3);
                }
                barx(2);
            }
            float bz0 = bias_s[r0], bz1 = bias_s[r0 + 1];
            float2 v;
            v = unpack2(a0); gate_x[r0 * 64 + b4 + 0] = v.x + bz0; gate_x[r0 * 64 + b4 + 1] = v.y + bz0;
            v = unpack2(a1); gate_x[r0 * 64 + b4 + 2] = v.x + bz0; gate_x[r0 * 64 + b4 + 3] = v.y + bz0;
            v = unpack2(a2); gate_x[(r0 + 1) * 64 + b4 + 0] = v.x + bz1; gate_x[(r0 + 1) * 64 + b4 + 1] = v.y + bz1;
            v = unpack2(a3); gate_x[(r0 + 1) * 64 + b4 + 2] = v.x + bz1; gate_x[(r0 + 1) * 64 + b4 + 3] = v.y + bz1;
        }

        __syncthreads();

        // ---------------- gate epilogue (all 256 threads, 1 element each) ----
        {
            float gi = gate_h[(0 * 4 + jj) * 64 + be] + gate_x[(0 * 4 + jj) * 64 + be];
            float gf = gate_h[(1 * 4 + jj) * 64 + be] + gate_x[(1 * 4 + jj) * 64 + be];
            float gg = gate_h[(2 * 4 + jj) * 64 + be] + gate_x[(2 * 4 + jj) * 64 + be];
            float go = gate_h[(3 * 4 + jj) * 64 + be] + gate_x[(3 * 4 + jj) * 64 + be];
            float iv = sigm(gi);
            float fv = sigm(gf);
            float gv = tanhf(gg);
            float ov = sigm(go);
            c_reg = fv * c_reg + iv * gv;
            float h = ov * tanhf(c_reg);
            __stcg(&g_hbuf[t & 1][(j0 + jj) * 64 + be], h);
            hout[jj * 64 + be] = h;
        }
        __threadfence();
        __syncthreads();
        if (tid == 0) st_rel(&g_flags[bid], base + (unsigned)t + 1u);

        // coalesced out write: thread b < 64 writes float4 [t][b][j0..j0+3]
        if (tid < 64) {
            float4 hv = make_float4(hout[tid], hout[64 + tid], hout[128 + tid], hout[192 + tid]);
            *(float4*)&out[((size_t)t * BB + tid) * HH + j0] = hv;
        }
    }
}

// ---------------- launch ----------------
extern "C" void kernel_launch(void* const* d_in, const int* in_sizes, int n_in,
                              void* d_out, int out_size)
{
    const float* x   = (const float*)d_in[0];
    const float* Wih = (const float*)d_in[1];
    const float* Whh = (const float*)d_in[2];
    const float* bih = (const float*)d_in[3];
    const float* bhh = (const float*)d_in[4];
    float* out = (float*)d_out;

    dim3 gT(HH / 64, TT);
    xT_kernel<<<gT, 256>>>(x);

    size_t smem = (size_t)SM_TOTAL_FLOATS * sizeof(float);
    cudaFuncSetAttribute(lstm_fused_kernel,
                         cudaFuncAttributeMaxDynamicSharedMemorySize, (int)smem);
    lstm_fused_kernel<<<128, 256, smem>>>(Wih, Whh, bih, bhh, out);
}

// round 10
// speedup vs baseline: 1.5212x; 1.5212x over previous
#include <cuda_runtime.h>
#include <cstdint>
#include <cstddef>

// LSTM T=512 B=64 I=H=512 fp32.
// K1: transpose x -> g_xT[t][i][b]
// K2: xproj GEMM -> g_xproj[t][g][b] (+both biases), 8x8 register tiles
// K3: persistent recurrence, 128 blocks x 256 thr, 16 half-warp k-covers

#define TT 512
#define BB 64
#define HH 512
#define GG 2048

typedef unsigned long long ull;

__device__ float    g_xT[(size_t)TT * HH * BB];
__device__ float    g_xproj[(size_t)TT * GG * BB];
__device__ float    g_hbuf[2][HH * BB];
__device__ unsigned g_flags[128];

// ---------------- helpers ----------------
__device__ __forceinline__ ull fma2(ull a, ull b, ull c) {
    ull d; asm("fma.rn.f32x2 %0, %1, %2, %3;" : "=l"(d) : "l"(a), "l"(b), "l"(c)); return d;
}
__device__ __forceinline__ ull pack2(float x, float y) {
    ull d; asm("mov.b64 %0, {%1, %2};" : "=l"(d) : "f"(x), "f"(y)); return d;
}
__device__ __forceinline__ float2 unpack2(ull v) {
    float2 r; asm("mov.b64 {%0, %1}, %2;" : "=f"(r.x), "=f"(r.y) : "l"(v)); return r;
}
__device__ __forceinline__ unsigned ld_acq(const unsigned* p) {
    unsigned v; asm volatile("ld.global.acquire.gpu.u32 %0, [%1];" : "=r"(v) : "l"(p)); return v;
}
__device__ __forceinline__ void st_rel(unsigned* p, unsigned v) {
    asm volatile("st.global.release.gpu.u32 [%0], %1;" :: "l"(p), "r"(v));
}
__device__ __forceinline__ float sigm(float x) { return 1.0f / (1.0f + __expf(-x)); }

__device__ __forceinline__ void cp_async16(uint32_t smem_addr, const void* gptr) {
    asm volatile("cp.async.cg.shared.global [%0], [%1], 16;" :: "r"(smem_addr), "l"(gptr));
}
#define CP_COMMIT() asm volatile("cp.async.commit_group;" ::: "memory")
#define CP_WAIT(n)  asm volatile("cp.async.wait_group " #n ";" ::: "memory")

// 8-row FMA: duplicated w into 4 batch-pair accumulators (uses locals x0,x1,a)
#define ROWF(i, wv) { ull wd = pack2(wv, wv); \
    a[i][0] = fma2(x0.x, wd, a[i][0]); a[i][1] = fma2(x0.y, wd, a[i][1]); \
    a[i][2] = fma2(x1.x, wd, a[i][2]); a[i][3] = fma2(x1.y, wd, a[i][3]); }

// ---------------- K1: x transpose to [t][i][b] ----------------
__global__ void __launch_bounds__(256) xT_kernel(const float* __restrict__ x)
{
    __shared__ float ts[64][65];
    const int t  = blockIdx.y;
    const int i0 = blockIdx.x * 64;
    const int tid = threadIdx.x;
#pragma unroll
    for (int p = 0; p < 16; ++p) {
        int lin = p * 256 + tid;
        int b = lin >> 6, i = lin & 63;
        ts[i][b] = x[((size_t)t * BB + b) * HH + i0 + i];
    }
    __syncthreads();
#pragma unroll
    for (int p = 0; p < 16; ++p) {
        int lin = p * 256 + tid;
        int i = lin >> 6, b = lin & 63;
        g_xT[((size_t)t * HH + i0 + i) * BB + b] = ts[i][b];
    }
}

// ---------------- K2: xproj GEMM ----------------
// Block: 256 g x 64 b at one t. 256 threads, per-thread 8g x 8b.
// thread mapping: g8=(tid&31)*8 (distinct within 8-lane phase), b8=(tid>>5)*8.
__global__ void __launch_bounds__(256) xproj_kernel(
    const float* __restrict__ Wih,
    const float* __restrict__ bih,
    const float* __restrict__ bhh)
{
    __shared__ float Wst[16 * 256];   // [k][g] 16KB
    __shared__ float Xst[16 * 64];    // [k][b] 4KB

    const int t   = blockIdx.y;
    const int g0  = blockIdx.x * 256;
    const int tid = threadIdx.x;
    const int g8  = (tid & 31) * 8;
    const int b8  = (tid >> 5) * 8;

    const float*  wsrc = Wih + (size_t)(g0 + tid) * HH;
    const float4* xsrc = (const float4*)(g_xT + (size_t)t * (HH * BB));

    float4 wpre[4];
#pragma unroll
    for (int q = 0; q < 4; ++q) wpre[q] = *(const float4*)(wsrc + q * 4);
    float4 xpre = __ldcs(xsrc + tid);

    ull a[8][4];
#pragma unroll
    for (int i = 0; i < 8; ++i)
#pragma unroll
        for (int j = 0; j < 4; ++j) a[i][j] = 0ull;

    for (int s = 0; s < 32; ++s) {
#pragma unroll
        for (int q = 0; q < 4; ++q) {
            Wst[(q * 4 + 0) * 256 + tid] = wpre[q].x;
            Wst[(q * 4 + 1) * 256 + tid] = wpre[q].y;
            Wst[(q * 4 + 2) * 256 + tid] = wpre[q].z;
            Wst[(q * 4 + 3) * 256 + tid] = wpre[q].w;
        }
        ((float4*)Xst)[tid] = xpre;
        __syncthreads();
        if (s < 31) {
#pragma unroll
            for (int q = 0; q < 4; ++q)
                wpre[q] = *(const float4*)(wsrc + (s + 1) * 16 + q * 4);
            xpre = __ldcs(xsrc + (s + 1) * 256 + tid);
        }
#pragma unroll
        for (int k = 0; k < 16; ++k) {
            float4 w0 = *(const float4*)&Wst[k * 256 + g8];
            float4 w1 = *(const float4*)&Wst[k * 256 + g8 + 4];
            ulonglong2 x0 = *(const ulonglong2*)&Xst[k * 64 + b8];
            ulonglong2 x1 = *(const ulonglong2*)&Xst[k * 64 + b8 + 4];
            ROWF(0, w0.x) ROWF(1, w0.y) ROWF(2, w0.z) ROWF(3, w0.w)
            ROWF(4, w1.x) ROWF(5, w1.y) ROWF(6, w1.z) ROWF(7, w1.w)
        }
        __syncthreads();
    }

    float* dst0 = g_xproj + ((size_t)t * GG + g0 + g8) * BB + b8;
#pragma unroll
    for (int i = 0; i < 8; ++i) {
        int g = g0 + g8 + i;
        float bi = bih[g] + bhh[g];
        float2 v0 = unpack2(a[i][0]), v1 = unpack2(a[i][1]);
        float2 v2 = unpack2(a[i][2]), v3 = unpack2(a[i][3]);
        float* dst = dst0 + (size_t)i * BB;
        *(float4*)dst       = make_float4(v0.x + bi, v0.y + bi, v1.x + bi, v1.y + bi);
        *(float4*)(dst + 4) = make_float4(v2.x + bi, v2.y + bi, v3.x + bi, v3.y + bi);
    }
}

// ---------------- K3: persistent recurrence ----------------
// SMEM floats: Wt[512][16]=8192 (32KB) | hs[512][64]=32768 (128KB) | hout 256
#define SMO_HS   8192
#define SMO_HOUT 40960
#define SM_FLOATS 41216

__global__ void __launch_bounds__(256, 1) lstm_rec_kernel(
    const float* __restrict__ Whh,
    float* __restrict__ out)
{
    extern __shared__ float sm[];
    float* Wt   = sm;                 // [k][r] 16 gate-rows
    float* hs   = sm + SMO_HS;        // [k][b]; cover kc owns [kc*32..+32)
    float* hout = sm + SMO_HOUT;

    const int tid = threadIdx.x;
    const int bid = blockIdx.x;
    const int j0  = bid * 4;

    // compute mapping: 16 covers x (2 row-groups x 8 batch-groups)
    const int kc    = tid >> 4;          // k-cover: k in [kc*32, kc*32+32)
    const int rg    = (tid >> 3) & 1;    // rows rg*8..rg*8+7
    const int bg    = tid & 7;           // batches bg*8..bg*8+7
    const int lid16 = tid & 15;
    const unsigned halfmask = (tid & 16) ? 0xFFFF0000u : 0x0000FFFFu;

    // epilogue mapping
    const int jj = tid >> 6;             // 0..3
    const int be = tid & 63;

    // ---- load W slice transposed: Wt[k][r], r = q*4+jj' ----
    {
        int r = tid >> 4, seg = tid & 15;
        int grow = (r >> 2) * HH + j0 + (r & 3);
        const float* src = Whh + (size_t)grow * HH + seg * 32;
#pragma unroll
        for (int q = 0; q < 32; q += 4) {
            float4 v = *(const float4*)(src + q);
            int k = seg * 32 + q;
            Wt[(k + 0) * 16 + r] = v.x;
            Wt[(k + 1) * 16 + r] = v.y;
            Wt[(k + 2) * 16 + r] = v.z;
            Wt[(k + 3) * 16 + r] = v.w;
        }
    }

    __shared__ unsigned s_base;
    if (tid == 0) s_base = ld_acq(&g_flags[bid]);
    __syncthreads();
    const unsigned base = s_base;

    float c_reg = 0.0f;

    const uint32_t hs_sm = (uint32_t)__cvta_generic_to_shared(hs + kc * 2048);
    const float* wbase = Wt + rg * 8;
    const float* hbase = hs + kc * 2048 + bg * 8;

    for (int t = 0; t < TT; ++t) {
        // prefetch x_proj for epilogue (independent of flags)
        const float* xpt = g_xproj + (size_t)t * (GG * BB) + (size_t)(j0 + jj) * BB + be;
        float xp0 = __ldcs(xpt);
        float xp1 = __ldcs(xpt + (size_t)HH * BB);
        float xp2 = __ldcs(xpt + (size_t)2 * HH * BB);
        float xp3 = __ldcs(xpt + (size_t)3 * HH * BB);

        if (t > 0) {
            // flag barrier: wait for all blocks to publish h(t-1)
            if (tid < 32) {
                unsigned tgt = base + (unsigned)t;
                for (;;) {
                    unsigned v0 = ld_acq(&g_flags[tid]);
                    unsigned v1 = ld_acq(&g_flags[tid + 32]);
                    unsigned v2 = ld_acq(&g_flags[tid + 64]);
                    unsigned v3 = ld_acq(&g_flags[tid + 96]);
                    bool ok = ((int)(v0 - tgt) >= 0) & ((int)(v1 - tgt) >= 0) &
                              ((int)(v2 - tgt) >= 0) & ((int)(v3 - tgt) >= 0);
                    if (__all_sync(0xffffffffu, ok)) break;
                    __nanosleep(32);
                }
            }
            __syncthreads();

            // cover kc stages its own 8KB h slice via cp.async, 4 groups of 8 k
            const float4* hsrc = (const float4*)(g_hbuf[(t + 1) & 1]) + kc * 512;
#pragma unroll
            for (int c = 0; c < 4; ++c) {
#pragma unroll
                for (int jq = 0; jq < 8; ++jq) {
                    int idx = lid16 + (c * 8 + jq) * 16;
                    cp_async16(hs_sm + idx * 16, hsrc + idx);
                }
                CP_COMMIT();
            }

            ull a[8][4];
#pragma unroll
            for (int i = 0; i < 8; ++i)
#pragma unroll
                for (int j = 0; j < 4; ++j) a[i][j] = 0ull;

#define REC_CHUNK(c) { \
    __syncwarp(halfmask); \
    _Pragma("unroll") \
    for (int kk = c * 8; kk < c * 8 + 8; ++kk) { \
        int k = kc * 32 + kk; \
        float4 w0 = *(const float4*)(wbase + k * 16); \
        float4 w1 = *(const float4*)(wbase + k * 16 + 4); \
        ulonglong2 x0 = *(const ulonglong2*)(hbase + kk * 64); \
        ulonglong2 x1 = *(const ulonglong2*)(hbase + kk * 64 + 4); \
        ROWF(0, w0.x) ROWF(1, w0.y) ROWF(2, w0.z) ROWF(3, w0.w) \
        ROWF(4, w1.x) ROWF(5, w1.y) ROWF(6, w1.z) ROWF(7, w1.w) \
    } }

            CP_WAIT(3); REC_CHUNK(0)
            CP_WAIT(2); REC_CHUNK(1)
            CP_WAIT(1); REC_CHUNK(2)
            CP_WAIT(0); REC_CHUNK(3)
#undef REC_CHUNK

            // write partials into own (now dead) h slice: ps[r][b] at hs[kc*2048]
            float* ps = hs + kc * 2048;
#pragma unroll
            for (int i = 0; i < 8; ++i) {
                float2 v0 = unpack2(a[i][0]), v1 = unpack2(a[i][1]);
                float2 v2 = unpack2(a[i][2]), v3 = unpack2(a[i][3]);
                float* row = ps + (rg * 8 + i) * 64 + bg * 8;
                *(float4*)row       = make_float4(v0.x, v0.y, v1.x, v1.y);
                *(float4*)(row + 4) = make_float4(v2.x, v2.y, v3.x, v3.y);
            }
        }
        __syncthreads();

        // ---- reduce 16 covers + gate math; thread owns (jj, be) ----
        float gi = xp0, gf = xp1, gg = xp2, go = xp3;
        if (t > 0) {
#pragma unroll
            for (int k16 = 0; k16 < 16; ++k16) {
                const float* ps = hs + k16 * 2048;
                gi += ps[(0 * 4 + jj) * 64 + be];
                gf += ps[(1 * 4 + jj) * 64 + be];
                gg += ps[(2 * 4 + jj) * 64 + be];
                go += ps[(3 * 4 + jj) * 64 + be];
            }
        }
        float iv = sigm(gi);
        float fv = sigm(gf);
        float gv = tanhf(gg);
        float ov = sigm(go);
        c_reg = fv * c_reg + iv * gv;
        float h = ov * tanhf(c_reg);
        __stcg(&g_hbuf[t & 1][(j0 + jj) * 64 + be], h);
        hout[jj * 64 + be] = h;

        __threadfence();
        __syncthreads();
        if (tid == 0) st_rel(&g_flags[bid], base + (unsigned)t + 1u);

        // coalesced out write: thread b writes float4 [t][b][j0..j0+3]
        if (tid < 64) {
            float4 hv = make_float4(hout[tid], hout[64 + tid], hout[128 + tid], hout[192 + tid]);
            *(float4*)&out[((size_t)t * BB + tid) * HH + j0] = hv;
        }
        __syncthreads();   // protect hout/hs reuse next step
    }
}

// ---------------- launch ----------------
extern "C" void kernel_launch(void* const* d_in, const int* in_sizes, int n_in,
                              void* d_out, int out_size)
{
    const float* x   = (const float*)d_in[0];
    const float* Wih = (const float*)d_in[1];
    const float* Whh = (const float*)d_in[2];
    const float* bih = (const float*)d_in[3];
    const float* bhh = (const float*)d_in[4];
    float* out = (float*)d_out;

    dim3 gT(HH / 64, TT);
    xT_kernel<<<gT, 256>>>(x);

    dim3 gP(GG / 256, TT);
    xproj_kernel<<<gP, 256>>>(Wih, bih, bhh);

    size_t smem = (size_t)SM_FLOATS * sizeof(float);
    cudaFuncSetAttribute(lstm_rec_kernel,
                         cudaFuncAttributeMaxDynamicSharedMemorySize, (int)smem);
    lstm_rec_kernel<<<128, 256, smem>>>(Whh, out);
}